// round 17
// baseline (speedup 1.0000x reference)
#include <cuda_runtime.h>
#include <cuda_fp16.h>
#include <cstdint>
#include <math.h>

// ---------------- static scratch ----------------
__device__ __align__(16) __half g_W13[25690112];     // [w1;w3] 2048x12544 fp16
__device__ __align__(16) __half g_w24[2097152];      // [w2;w4] 2048x1024 fp16
__device__ __align__(16) __half g_act16[16777216];   // 8192x2048 fp16 (act1)
__device__ __align__(16) __half g_act2[16777216];    // 8192x2048 fp16 (act2)
__device__ __align__(16) __half g_whead[131072];     // 64x2048 fp16 zero-padded head weights
__device__ float g_hbias[64];
__device__ __align__(16) float  g_heads[524288];     // 8192x64

// ---------------- helpers ----------------
__device__ __forceinline__ uint32_t smem_u32(const void* p) {
    uint32_t a;
    asm("{ .reg .u64 t; cvta.to.shared.u64 t, %1; cvt.u32.u64 %0, t; }" : "=r"(a) : "l"(p));
    return a;
}
__device__ __forceinline__ uint32_t swz128(uint32_t x) { return x ^ ((x >> 3) & 0x70); }

__device__ __forceinline__ void cp16(uint32_t dst, const void* src) {
    asm volatile("cp.async.cg.shared.global [%0], [%1], 16;"
                 :: "r"(dst), "l"(__cvta_generic_to_global(src)) : "memory");
}
#define CP_COMMIT() asm volatile("cp.async.commit_group;" ::: "memory")
#define CP_WAIT2()  asm volatile("cp.async.wait_group 2;" ::: "memory")

__device__ __forceinline__ void ldsm4(uint32_t* r, uint32_t a) {
    asm volatile("ldmatrix.sync.aligned.m8n8.x4.shared.b16 {%0,%1,%2,%3}, [%4];"
                 : "=r"(r[0]), "=r"(r[1]), "=r"(r[2]), "=r"(r[3]) : "r"(a));
}
__device__ __forceinline__ void mma_f16(float* d, const uint32_t* a, uint32_t b0, uint32_t b1) {
    asm volatile(
        "mma.sync.aligned.m16n8k16.row.col.f32.f16.f16.f32 "
        "{%0,%1,%2,%3}, {%4,%5,%6,%7}, {%8,%9}, {%0,%1,%2,%3};"
        : "+f"(d[0]), "+f"(d[1]), "+f"(d[2]), "+f"(d[3])
        : "r"(a[0]), "r"(a[1]), "r"(a[2]), "r"(a[3]), "r"(b0), "r"(b1));
}
__device__ __forceinline__ uint32_t h2u(__half2 h) { return *reinterpret_cast<uint32_t*>(&h); }

// stage: A16 16K | B 16K = 32KB, 3 stages = 96KB, 2 CTAs/SM
static constexpr int STG = 32768;
static constexpr int SMEM_BYTES = 3 * STG;

// ============ GEMM1 fused: C = relu(fp32 A @ W13^T + b) -> fp16 g_act16 ====
// A read as fp32, converted in registers, STS fp16. 128 threads, warp 64x64.
__global__ void __launch_bounds__(128, 2) gemm1_fused(
    const float* __restrict__ A,
    const float* __restrict__ b1, const float* __restrict__ b3)
{
    extern __shared__ char smem[];
    const uint32_t sbase = smem_u32(smem);
    const int tid = threadIdx.x, wid = tid >> 5, lid = tid & 31;
    const int n_base = blockIdx.x * 128;
    const int m_base = blockIdx.y * 128;
    const float* bias = (n_base >= 1024) ? b3 : b1;
    const __half* B = g_W13;
    const int K = 12544, NS = 196;

    const int m0 = (wid & 1) * 64, n0 = (wid >> 1) * 64;
    const int lrow = lid & 15, lcol = (lid >> 4) * 16;
    const int ld_r0 = tid >> 3, ld_c = tid & 7;

    float acc[4][8][4];
#pragma unroll
    for (int mt = 0; mt < 4; ++mt)
#pragma unroll
        for (int j = 0; j < 8; ++j)
#pragma unroll
            for (int q = 0; q < 4; ++q) acc[mt][j][q] = 0.f;

    // each thread owns one A row (row = tid), 64 fp32 per stage = 16 float4
    const float* a_row = A + (size_t)(m_base + tid) * K;
    float4 areg[16];

    auto ldg_A = [&](int s) {
        if (s < NS) {
            const float* p = a_row + (size_t)s * 64;
#pragma unroll
            for (int j = 0; j < 16; ++j)
                areg[j] = __ldg(reinterpret_cast<const float4*>(p) + j);
        }
    };
    auto sts_A = [&](int s) {
        if (s < NS) {
            const uint32_t so = sbase + (uint32_t)(s % 3) * STG;
#pragma unroll
            for (int c = 0; c < 8; ++c) {
                float4 v0 = areg[2 * c], v1 = areg[2 * c + 1];
                uint4 o;
                o.x = h2u(__floats2half2_rn(v0.x, v0.y));
                o.y = h2u(__floats2half2_rn(v0.z, v0.w));
                o.z = h2u(__floats2half2_rn(v1.x, v1.y));
                o.w = h2u(__floats2half2_rn(v1.z, v1.w));
                *reinterpret_cast<uint4*>(smem + (so - sbase) +
                    swz128((uint32_t)(tid * 128 + c * 16))) = o;
            }
        }
    };
    auto cp_B = [&](int s) {
        if (s < NS) {
            const size_t kb = (size_t)s * 64;
            const uint32_t so = sbase + (uint32_t)(s % 3) * STG;
#pragma unroll
            for (int i = 0; i < 8; ++i) {
                const int row = ld_r0 + i * 16;
                cp16(so + 16384 + swz128((uint32_t)(row * 128 + ld_c * 16)),
                     B + (size_t)(n_base + row) * K + kb + ld_c * 8);
            }
        }
        CP_COMMIT();
    };

    // prologue: smem <- A0,A1 ; regs <- A2 ; B0,B1 in flight
    ldg_A(0); cp_B(0); sts_A(0);
    ldg_A(1); cp_B(1); sts_A(1);
    ldg_A(2);

#pragma unroll 1
    for (int s = 0; s < NS; ++s) {
        sts_A(s + 2);          // regs hold A(s+2); buffer (s+2)%3 freed by end-sync of s-1
        ldg_A(s + 3);          // prefetch next into regs
        cp_B(s + 2);
        CP_WAIT2();
        __syncthreads();
        const uint32_t so = sbase + (uint32_t)(s % 3) * STG;
#pragma unroll
        for (int kk = 0; kk < 4; ++kk) {
            const int kb2 = kk * 32;
            uint32_t af[4][4];
#pragma unroll
            for (int mt = 0; mt < 4; ++mt)
                ldsm4(af[mt], so + swz128((uint32_t)((m0 + mt * 16 + lrow) * 128 + kb2 + lcol)));
#pragma unroll
            for (int j2 = 0; j2 < 4; ++j2) {
                uint32_t bf[4];
                ldsm4(bf, so + 16384 +
                      swz128((uint32_t)((n0 + j2 * 16 + lrow) * 128 + kb2 + lcol)));
#pragma unroll
                for (int mt = 0; mt < 4; ++mt)
#pragma unroll
                    for (int h = 0; h < 2; ++h)
                        mma_f16(acc[mt][j2 * 2 + h], af[mt], bf[h], bf[2 + h]);
            }
        }
        __syncthreads();
    }

    const int grp = lid >> 2, qd = lid & 3;
#pragma unroll
    for (int mt = 0; mt < 4; ++mt)
#pragma unroll
        for (int j = 0; j < 8; ++j)
#pragma unroll
            for (int h = 0; h < 2; ++h) {
                const int row = m_base + m0 + mt * 16 + grp + h * 8;
                const int colg = n_base + n0 + (j >> 1) * 16 + (j & 1) * 8 + qd * 2;
                const int cb = colg & 1023;
                float v0 = fmaxf(acc[mt][j][2 * h]     + __ldg(bias + cb), 0.f);
                float v1 = fmaxf(acc[mt][j][2 * h + 1] + __ldg(bias + cb + 1), 0.f);
                __half2 p = __floats2half2_rn(v0, v1);
                *reinterpret_cast<uint32_t*>(g_act16 + (size_t)row * 2048 + colg) = h2u(p);
            }
}

// ============ GEMM2: act1 @ w24^T -> fp16 g_act2 (all fp16 cp.async) ============
__global__ void __launch_bounds__(128, 2) gemm2_kernel(
    const float* __restrict__ biasA, const float* __restrict__ biasB)
{
    extern __shared__ char smem[];
    const uint32_t sbase = smem_u32(smem);
    const int tid = threadIdx.x, wid = tid >> 5, lid = tid & 31;
    const int n_base = blockIdx.x * 128;
    const int m_base = blockIdx.y * 128;
    const int a_off = (n_base >= 1024) ? 1024 : 0;
    const float* bias = (n_base >= 1024) ? biasB : biasA;
    const int K = 1024, ldA = 2048, NS = 16;

    const int m0 = (wid & 1) * 64, n0 = (wid >> 1) * 64;
    const int lrow = lid & 15, lcol = (lid >> 4) * 16;
    const int ld_r0 = tid >> 3, ld_c = tid & 7;

    float acc[4][8][4];
#pragma unroll
    for (int mt = 0; mt < 4; ++mt)
#pragma unroll
        for (int j = 0; j < 8; ++j)
#pragma unroll
            for (int q = 0; q < 4; ++q) acc[mt][j][q] = 0.f;

    auto load_stage = [&](int s) {
        if (s < NS) {
            const size_t kb = (size_t)s * 64;
            const uint32_t so = sbase + (uint32_t)(s % 3) * STG;
#pragma unroll
            for (int i = 0; i < 8; ++i) {
                const int row = ld_r0 + i * 16;
                const uint32_t sw = swz128((uint32_t)(row * 128 + ld_c * 16));
                cp16(so + sw,
                     g_act16 + (size_t)(m_base + row) * ldA + a_off + kb + ld_c * 8);
                cp16(so + 16384 + sw,
                     g_w24 + (size_t)(n_base + row) * K + kb + ld_c * 8);
            }
        }
        CP_COMMIT();
    };

    load_stage(0);
    load_stage(1);

#pragma unroll 1
    for (int s = 0; s < NS; ++s) {
        load_stage(s + 2);
        CP_WAIT2();
        __syncthreads();
        const uint32_t so = sbase + (uint32_t)(s % 3) * STG;
#pragma unroll
        for (int kk = 0; kk < 4; ++kk) {
            const int kb2 = kk * 32;
            uint32_t af[4][4];
#pragma unroll
            for (int mt = 0; mt < 4; ++mt)
                ldsm4(af[mt], so + swz128((uint32_t)((m0 + mt * 16 + lrow) * 128 + kb2 + lcol)));
#pragma unroll
            for (int j2 = 0; j2 < 4; ++j2) {
                uint32_t bf[4];
                ldsm4(bf, so + 16384 +
                      swz128((uint32_t)((n0 + j2 * 16 + lrow) * 128 + kb2 + lcol)));
#pragma unroll
                for (int mt = 0; mt < 4; ++mt)
#pragma unroll
                    for (int h = 0; h < 2; ++h)
                        mma_f16(acc[mt][j2 * 2 + h], af[mt], bf[h], bf[2 + h]);
            }
        }
        __syncthreads();
    }

    const int grp = lid >> 2, qd = lid & 3;
#pragma unroll
    for (int mt = 0; mt < 4; ++mt)
#pragma unroll
        for (int j = 0; j < 8; ++j)
#pragma unroll
            for (int h = 0; h < 2; ++h) {
                const int row = m_base + m0 + mt * 16 + grp + h * 8;
                const int colg = n_base + n0 + (j >> 1) * 16 + (j & 1) * 8 + qd * 2;
                const int cb = colg & 1023;
                float v0 = fmaxf(acc[mt][j][2 * h]     + __ldg(bias + cb), 0.f);
                float v1 = fmaxf(acc[mt][j][2 * h + 1] + __ldg(bias + cb + 1), 0.f);
                __half2 p = __floats2half2_rn(v0, v1);
                *reinterpret_cast<uint32_t*>(g_act2 + (size_t)row * 2048 + colg) = h2u(p);
            }
}

// ============ Heads GEMM: [8192,2048] x whead^T[2048,64] -> g_heads fp32 ====
static constexpr int HSTG = 16384;
static constexpr int HSMEM = 3 * HSTG;

__global__ void __launch_bounds__(128, 2) heads_gemm()
{
    extern __shared__ char smem[];
    const uint32_t sbase = smem_u32(smem);
    const int tid = threadIdx.x, wid = tid >> 5, lid = tid & 31;
    const int m_base = blockIdx.x * 64;
    const int NS = 32;

    const int m0 = (wid & 1) * 32, n0 = (wid >> 1) * 32;
    const int lrow = lid & 15, lcol = (lid >> 4) * 16;
    const int ld_r0 = tid >> 3, ld_c = tid & 7;

    float acc[2][4][4];
#pragma unroll
    for (int mt = 0; mt < 2; ++mt)
#pragma unroll
        for (int j = 0; j < 4; ++j)
#pragma unroll
            for (int q = 0; q < 4; ++q) acc[mt][j][q] = 0.f;

    auto load_stage = [&](int s) {
        if (s < NS) {
            const size_t kb = (size_t)s * 64;
            const uint32_t so = sbase + (uint32_t)(s % 3) * HSTG;
#pragma unroll
            for (int i = 0; i < 4; ++i) {
                const int row = ld_r0 + i * 16;
                const uint32_t sw = swz128((uint32_t)(row * 128 + ld_c * 16));
                cp16(so + sw, g_act2 + (size_t)(m_base + row) * 2048 + kb + ld_c * 8);
                cp16(so + 8192 + sw, g_whead + (size_t)row * 2048 + kb + ld_c * 8);
            }
        }
        CP_COMMIT();
    };

    load_stage(0);
    load_stage(1);

#pragma unroll 1
    for (int s = 0; s < NS; ++s) {
        load_stage(s + 2);
        CP_WAIT2();
        __syncthreads();
        const uint32_t so = sbase + (uint32_t)(s % 3) * HSTG;
#pragma unroll
        for (int kk = 0; kk < 4; ++kk) {
            const int kb2 = kk * 32;
            uint32_t af[2][4];
#pragma unroll
            for (int mt = 0; mt < 2; ++mt)
                ldsm4(af[mt], so + swz128((uint32_t)((m0 + mt * 16 + lrow) * 128 + kb2 + lcol)));
#pragma unroll
            for (int j2 = 0; j2 < 2; ++j2) {
                uint32_t bf[4];
                ldsm4(bf, so + 8192 +
                      swz128((uint32_t)((n0 + j2 * 16 + lrow) * 128 + kb2 + lcol)));
#pragma unroll
                for (int mt = 0; mt < 2; ++mt)
#pragma unroll
                    for (int h = 0; h < 2; ++h)
                        mma_f16(acc[mt][j2 * 2 + h], af[mt], bf[h], bf[2 + h]);
            }
        }
        __syncthreads();
    }

    const int grp = lid >> 2, qd = lid & 3;
#pragma unroll
    for (int mt = 0; mt < 2; ++mt)
#pragma unroll
        for (int j = 0; j < 4; ++j)
#pragma unroll
            for (int h = 0; h < 2; ++h) {
                const int row = m_base + m0 + mt * 16 + grp + h * 8;
                const int colg = n0 + (j >> 1) * 16 + (j & 1) * 8 + qd * 2;
                float2 f;
                f.x = acc[mt][j][2 * h]     + g_hbias[colg];
                f.y = acc[mt][j][2 * h + 1] + g_hbias[colg + 1];
                *reinterpret_cast<float2*>(g_heads + (size_t)row * 64 + colg) = f;
            }
}

// ============ fp32 -> fp16 conversion ============
__global__ void __launch_bounds__(256) conv_half(
    const float* __restrict__ s, __half* __restrict__ d, size_t n4)
{
    const size_t i = (size_t)blockIdx.x * 256 + threadIdx.x;
    if (i >= n4) return;
    float4 v = reinterpret_cast<const float4*>(s)[i];
    __half2 p0 = __floats2half2_rn(v.x, v.y);
    __half2 p1 = __floats2half2_rn(v.z, v.w);
    uint2 o; o.x = h2u(p0); o.y = h2u(p1);
    reinterpret_cast<uint2*>(d)[i] = o;
}

// ============ pack head weights ============
__global__ void __launch_bounds__(256) pack_heads(
    const float* __restrict__ w_cls, const float* __restrict__ b_cls,
    const float* __restrict__ w_delta, const float* __restrict__ b_delta,
    const float* __restrict__ w_pos, const float* __restrict__ b_pos,
    const float* __restrict__ w_emb, const float* __restrict__ b_emb)
{
    const int idx = blockIdx.x * 256 + threadIdx.x;
    if (idx >= 131072) return;
    const int o = idx >> 11, c = idx & 2047;
    float v = 0.f;
    if (o < 3)       { if (c < 1024)  v = w_cls[o * 1024 + c]; }
    else if (o < 15) { if (c < 1024)  v = w_delta[(o - 3) * 1024 + c]; }
    else if (o < 21) { if (c < 1024)  v = w_pos[(o - 15) * 1024 + c]; }
    else if (o < 53) { if (c >= 1024) v = w_emb[(o - 21) * 1024 + (c - 1024)]; }
    g_whead[idx] = __float2half_rn(v);
    if (idx < 64) {
        float b = 0.f;
        if (idx < 3)       b = b_cls[idx];
        else if (idx < 15) b = b_delta[idx - 3];
        else if (idx < 21) b = b_pos[idx - 15];
        else if (idx < 53) b = b_emb[idx - 21];
        g_hbias[idx] = b;
    }
}

// ============ Postprocess ============
__global__ void __launch_bounds__(128) post_kernel(
    const float* __restrict__ rois, float* __restrict__ out, int out_size)
{
    const int n = blockIdx.x * blockDim.x + threadIdx.x;
    if (n >= 8192) return;
    const float* h = g_heads + (size_t)n * 64;
    float c0 = h[0], c1 = h[1], c2 = h[2];
    float m = fmaxf(c0, fmaxf(c1, c2));
    float e0 = expf(c0 - m), e1 = expf(c1 - m), e2 = expf(c2 - m);
    float inv = 1.f / (e0 + e1 + e2);
    float sc0 = e1 * inv, sc1 = e2 * inv;
    float x1 = rois[n * 5 + 1], y1 = rois[n * 5 + 2];
    float x2 = rois[n * 5 + 3], y2 = rois[n * 5 + 4];
    float bw = x2 - x1, bh = y2 - y1;
    float cx = x1 + 0.5f * bw, cy = y1 + 0.5f * bh;
#pragma unroll
    for (int j = 0; j < 2; ++j) {
        float d0 = h[7 + 4 * j] * 0.1f, d1 = h[8 + 4 * j] * 0.1f;
        float d2 = h[9 + 4 * j] * 0.2f, d3 = h[10 + 4 * j] * 0.2f;
        float p0 = h[17 + 2 * j] * 0.1f, p1 = h[18 + 2 * j] * 0.1f;
        float pcx = d0 * bw + cx, pcy = d1 * bh + cy;
        float pw = expf(d2) * bw, phh = expf(d3) * bh;
        float px = p0 * bw + cx, py = p1 * bh + cy;
        float* ob = out + (size_t)(2 * n + j) * 8;
        ob[0] = pcx - 0.5f * pw;  ob[1] = pcy - 0.5f * phh;
        ob[2] = pcx + 0.5f * pw;  ob[3] = pcy + 0.5f * phh;
        ob[4] = px; ob[5] = py;
        ob[6] = j ? sc1 : sc0;
        ob[7] = (float)(j + 1);
        float* oe = out + 131072 + (size_t)(2 * n + j) * 32;
#pragma unroll
        for (int t = 0; t < 32; ++t) oe[t] = h[21 + t];
    }
    if (n == 0 && out_size > 655360) out[655360] = 2.0f;
}

// ============ launch ============
extern "C" void kernel_launch(void* const* d_in, const int* in_sizes, int n_in,
                              void* d_out, int out_size) {
    const float* pool   = (const float*)d_in[0];
    const float* rois   = (const float*)d_in[1];
    const float* w_fc1  = (const float*)d_in[2];
    const float* b_fc1  = (const float*)d_in[3];
    const float* w_fc2  = (const float*)d_in[4];
    const float* b_fc2  = (const float*)d_in[5];
    const float* w_fc3  = (const float*)d_in[6];
    const float* b_fc3  = (const float*)d_in[7];
    const float* w_fc4  = (const float*)d_in[8];
    const float* b_fc4  = (const float*)d_in[9];
    const float* w_cls  = (const float*)d_in[10];
    const float* b_cls  = (const float*)d_in[11];
    const float* w_delta= (const float*)d_in[12];
    const float* b_delta= (const float*)d_in[13];
    const float* w_pos  = (const float*)d_in[14];
    const float* b_pos  = (const float*)d_in[15];
    const float* w_emb  = (const float*)d_in[16];
    const float* b_emb  = (const float*)d_in[17];
    float* out = (float*)d_out;

    __half *W13, *W24;
    cudaGetSymbolAddress((void**)&W13, g_W13);
    cudaGetSymbolAddress((void**)&W24, g_w24);

    cudaFuncSetAttribute(gemm1_fused,  cudaFuncAttributeMaxDynamicSharedMemorySize, SMEM_BYTES);
    cudaFuncSetAttribute(gemm2_kernel, cudaFuncAttributeMaxDynamicSharedMemorySize, SMEM_BYTES);
    cudaFuncSetAttribute(heads_gemm,   cudaFuncAttributeMaxDynamicSharedMemorySize, HSMEM);

    // 5 prep launches; gemm1_fused = launch #6 (ncu -s 5 -c 1 target)
    conv_half<<<12544, 256>>>(w_fc1, W13,            3211264);   // L1
    conv_half<<<12544, 256>>>(w_fc3, W13 + 12845056, 3211264);   // L2
    conv_half<<<1024,  256>>>(w_fc2, W24,            262144);    // L3
    conv_half<<<1024,  256>>>(w_fc4, W24 + 1048576,  262144);    // L4
    pack_heads<<<512,  256>>>(w_cls, b_cls, w_delta, b_delta,
                              w_pos, b_pos, w_emb, b_emb);       // L5

    gemm1_fused<<<dim3(16, 64), 128, SMEM_BYTES>>>(pool, b_fc1, b_fc3);        // L6
    gemm2_kernel<<<dim3(16, 64), 128, SMEM_BYTES>>>(b_fc2, b_fc4);
    heads_gemm<<<128, 128, HSMEM>>>();
    post_kernel<<<64, 128>>>(rois, out, out_size);
}